// round 9
// baseline (speedup 1.0000x reference)
#include <cuda_runtime.h>
#include <cuda_fp16.h>
#include <cstdint>

#define BB 4
#define SS 4096
#define DD 64
#define QT 128
#define KT 128
#define NTH 256
#define NCHUNK (SS / KT)
#define VSTR 72   // fp16 elems per smem row (144B: conflict-free ldmatrix)

#define TILE_BYTES (QT * VSTR * 2)          // 18432
#define BUF_BYTES  (2 * TILE_BYTES)         // H + L
#define SMEM_TOTAL (2 * BUF_BYTES)          // 73728

#define GROWS (BB * SS)

// per-row softmax stats scratch
__device__ float g_rowm[GROWS];
__device__ float g_rowz[GROWS];

#define NEGINF __int_as_float(0xff800000)

static __device__ __forceinline__ uint32_t smem_u32(const void* p) {
    uint32_t a;
    asm("{ .reg .u64 t; cvta.to.shared.u64 t, %1; cvt.u32.u64 %0, t; }" : "=r"(a) : "l"(p));
    return a;
}

static __device__ __forceinline__ uint32_t pack_f16(float lo, float hi) {
    uint32_t r;
    asm("cvt.rn.f16x2.f32 %0, %1, %2;" : "=r"(r) : "f"(hi), "f"(lo));
    return r;
}

#define LDSM4(r, a) \
    asm volatile("ldmatrix.sync.aligned.m8n8.x4.shared.b16 {%0,%1,%2,%3}, [%4];" \
                 : "=r"((r)[0]), "=r"((r)[1]), "=r"((r)[2]), "=r"((r)[3]) : "r"(a))

#define LDSM4T(r, a) \
    asm volatile("ldmatrix.sync.aligned.m8n8.x4.trans.shared.b16 {%0,%1,%2,%3}, [%4];" \
                 : "=r"((r)[0]), "=r"((r)[1]), "=r"((r)[2]), "=r"((r)[3]) : "r"(a))

static __device__ __forceinline__ void mma16816(float* d, const uint32_t* a,
                                                uint32_t b0, uint32_t b1) {
    asm volatile(
        "mma.sync.aligned.m16n8k16.row.col.f32.f16.f16.f32 "
        "{%0,%1,%2,%3}, {%4,%5,%6,%7}, {%8,%9}, {%0,%1,%2,%3};"
        : "+f"(d[0]), "+f"(d[1]), "+f"(d[2]), "+f"(d[3])
        : "r"(a[0]), "r"(a[1]), "r"(a[2]), "r"(a[3]), "r"(b0), "r"(b1));
}

// split fp32x4 -> hi/lo fp16x2 pairs into the H/L tiles
static __device__ __forceinline__ void split_store(char* smbase, uint32_t off,
                                                   float4 v) {
    __half hx = __float2half_rn(v.x);
    __half hy = __float2half_rn(v.y);
    __half hz = __float2half_rn(v.z);
    __half hw = __float2half_rn(v.w);
    uint2 H, L;
    H.x = pack_f16(v.x, v.y);
    H.y = pack_f16(v.z, v.w);
    L.x = pack_f16(v.x - __half2float(hx), v.y - __half2float(hy));
    L.y = pack_f16(v.z - __half2float(hz), v.w - __half2float(hw));
    *(uint2*)(smbase + off)              = H;
    *(uint2*)(smbase + off + TILE_BYTES) = L;
}

// Main kernel: flash-style, software-pipelined within each chunk.
__global__ void __launch_bounds__(NTH, 1)
attn_mma_kernel(const float* __restrict__ Q, const float* __restrict__ V,
                float* __restrict__ ctx_out, float* __restrict__ attn_out)
{
    extern __shared__ __align__(16) char smraw[];   // [buf0 H|L][buf1 H|L]

    const int tid  = threadIdx.x;
    const int w    = tid >> 5;
    const int lane = tid & 31;
    const int g    = lane >> 2;
    const int p    = lane & 3;
    const int b    = blockIdx.y;
    const int q0   = blockIdx.x * QT;

    const float* Qg = Q + (size_t)(b * SS + q0) * DD;
    const float* Vg = V + (size_t)b * SS * DD;

    const uint32_t sbase = smem_u32(smraw);

    const int ldq  = tid >> 4;
    const int ldd4 = (tid & 15) * 4;
    const uint32_t stoff = (uint32_t)(ldq * VSTR + ldd4) * 2;

    // ---- stage Q -> buf0 hi/lo ----
    #pragma unroll
    for (int r = 0; r < 8; r++) {
        int lin = tid + r * NTH;
        int q  = lin >> 4;
        int d4 = (lin & 15) * 4;
        float4 v = *(const float4*)(Qg + q * DD + d4);
        split_store(smraw, (uint32_t)(q * VSTR + d4) * 2, v);
    }
    __syncthreads();

    const int rA = (lane & 7) + ((lane >> 3) & 1) * 8;
    const int kA = (lane >> 4) * 8;
    const int rB = (lane & 7) + (lane >> 4) * 8;
    const int kB = ((lane >> 3) & 1) * 8;

    uint32_t qh[4][4], ql[4][4];
    #pragma unroll
    for (int ks = 0; ks < 4; ks++) {
        uint32_t off = (uint32_t)((w * 16 + rA) * VSTR + ks * 16 + kA) * 2;
        LDSM4(qh[ks], sbase + off);
        LDSM4(ql[ks], sbase + off + TILE_BYTES);
    }
    __syncthreads();

    float m0 = NEGINF, m1 = NEGINF, z0 = 0.0f, z1 = 0.0f;
    float cacc[8][4];
    #pragma unroll
    for (int j = 0; j < 8; j++)
        #pragma unroll
        for (int e = 0; e < 4; e++) cacc[j][e] = 0.0f;

    float4 pv[8];
    #pragma unroll
    for (int r = 0; r < 8; r++)
        pv[r] = *(const float4*)(Vg + (size_t)(r * 16 + ldq) * DD + ldd4);

    for (int c = 0; c < NCHUNK; c++) {
        char*    smb = smraw + (c & 1) * BUF_BYTES;
        uint32_t sb  = sbase + (c & 1) * BUF_BYTES;

        #pragma unroll
        for (int r = 0; r < 8; r++)
            split_store(smb, stoff + (uint32_t)(r * 16 * VSTR) * 2, pv[r]);
        __syncthreads();

        if (c + 1 < NCHUNK) {
            const float* vn = Vg + (size_t)((c + 1) * KT + ldq) * DD + ldd4;
            #pragma unroll
            for (int r = 0; r < 8; r++)
                pv[r] = *(const float4*)(vn + (size_t)(r * 16) * DD);
        }

        float* srow0 = attn_out + (size_t)(b * SS + q0 + w * 16 + g) * SS + c * KT + 2 * p;
        float* srow1 = srow0 + (size_t)8 * SS;

        // ---- GEMM1 np-outer: finish 16 cols, then STG + max WHILE next np's
        //      MMAs issue ----
        float sacc[16][4];
        float ml0 = NEGINF, ml1 = NEGINF;
        #pragma unroll
        for (int np = 0; np < 8; np++) {
            float* sa0 = sacc[2 * np];
            float* sa1 = sacc[2 * np + 1];
            #pragma unroll
            for (int e = 0; e < 4; e++) { sa0[e] = 0.0f; sa1[e] = 0.0f; }
            #pragma unroll
            for (int ks = 0; ks < 4; ks++) {
                uint32_t off = (uint32_t)((np * 16 + rB) * VSTR + ks * 16 + kB) * 2;
                uint32_t bh[4], bl[4];
                LDSM4(bh, sb + off);
                LDSM4(bl, sb + off + TILE_BYTES);
                mma16816(sa0, qh[ks], bh[0], bh[1]);
                mma16816(sa1, qh[ks], bh[2], bh[3]);
                mma16816(sa0, qh[ks], bl[0], bl[1]);
                mma16816(sa1, qh[ks], bl[2], bl[3]);
                mma16816(sa0, ql[ks], bh[0], bh[1]);
                mma16816(sa1, ql[ks], bh[2], bh[3]);
            }
            // immediate raw-score store + running max (overlaps next np)
            *(float2*)(srow0 + 16 * np)     = make_float2(sa0[0], sa0[1]);
            *(float2*)(srow0 + 16 * np + 8) = make_float2(sa1[0], sa1[1]);
            *(float2*)(srow1 + 16 * np)     = make_float2(sa0[2], sa0[3]);
            *(float2*)(srow1 + 16 * np + 8) = make_float2(sa1[2], sa1[3]);
            ml0 = fmaxf(ml0, fmaxf(fmaxf(sa0[0], sa0[1]), fmaxf(sa1[0], sa1[1])));
            ml1 = fmaxf(ml1, fmaxf(fmaxf(sa0[2], sa0[3]), fmaxf(sa1[2], sa1[3])));
        }

        // ---- row max across quad + rescale ----
        #pragma unroll
        for (int off = 1; off <= 2; off <<= 1) {
            ml0 = fmaxf(ml0, __shfl_xor_sync(0xffffffffu, ml0, off));
            ml1 = fmaxf(ml1, __shfl_xor_sync(0xffffffffu, ml1, off));
        }
        float mn0 = fmaxf(m0, ml0), mn1 = fmaxf(m1, ml1);
        float sc0 = __expf(m0 - mn0), sc1 = __expf(m1 - mn1);
        m0 = mn0; m1 = mn1;

        #pragma unroll
        for (int j = 0; j < 8; j++) {
            cacc[j][0] *= sc0; cacc[j][1] *= sc0;
            cacc[j][2] *= sc1; cacc[j][3] *= sc1;
        }

        // ---- GEMM2 with fused exp: MUFU overlaps tensor pipe ----
        float s0 = 0.0f, s1 = 0.0f;
        #pragma unroll
        for (int kk = 0; kk < 8; kk++) {
            float e00 = __expf(sacc[2 * kk][0] - mn0);
            float e01 = __expf(sacc[2 * kk][1] - mn0);
            float e02 = __expf(sacc[2 * kk][2] - mn1);
            float e03 = __expf(sacc[2 * kk][3] - mn1);
            float e10 = __expf(sacc[2 * kk + 1][0] - mn0);
            float e11 = __expf(sacc[2 * kk + 1][1] - mn0);
            float e12 = __expf(sacc[2 * kk + 1][2] - mn1);
            float e13 = __expf(sacc[2 * kk + 1][3] - mn1);
            s0 += (e00 + e01) + (e10 + e11);
            s1 += (e02 + e03) + (e12 + e13);
            uint32_t ah[4];
            ah[0] = pack_f16(e00, e01);
            ah[1] = pack_f16(e02, e03);
            ah[2] = pack_f16(e10, e11);
            ah[3] = pack_f16(e12, e13);
            #pragma unroll
            for (int np = 0; np < 4; np++) {
                uint32_t off = (uint32_t)((kk * 16 + rA) * VSTR + np * 16 + kA) * 2;
                uint32_t bh[4];
                LDSM4T(bh, sb + off);
                mma16816(cacc[2 * np],     ah, bh[0], bh[1]);
                mma16816(cacc[2 * np + 1], ah, bh[2], bh[3]);
            }
        }
        #pragma unroll
        for (int off = 1; off <= 2; off <<= 1) {
            s0 += __shfl_xor_sync(0xffffffffu, s0, off);
            s1 += __shfl_xor_sync(0xffffffffu, s1, off);
        }
        z0 = z0 * sc0 + s0;
        z1 = z1 * sc1 + s1;
    }

    // ---- epilogue ----
    const float iz0 = 1.0f / z0, iz1 = 1.0f / z1;
    {
        float* crow0 = ctx_out + (size_t)(b * SS + q0 + w * 16 + g) * DD + 2 * p;
        float* crow1 = crow0 + (size_t)8 * DD;
        #pragma unroll
        for (int j = 0; j < 8; j++) {
            *(float2*)(crow0 + 8 * j) = make_float2(cacc[j][0] * iz0, cacc[j][1] * iz0);
            *(float2*)(crow1 + 8 * j) = make_float2(cacc[j][2] * iz1, cacc[j][3] * iz1);
        }
    }
    if (p == 0) {
        int row = b * SS + q0 + w * 16 + g;
        g_rowm[row]     = m0;
        g_rowz[row]     = z0;
        g_rowm[row + 8] = m1;
        g_rowz[row + 8] = z1;
    }
}

// Norm kernel: w = exp(s - m)/Z in place. High columns first (L2-resident),
// allocating loads, streaming stores.
__global__ void __launch_bounds__(512)
attn_norm_kernel(float* __restrict__ attn)
{
    const int row = blockIdx.x;
    const float m = g_rowm[row];
    const float r = 1.0f / g_rowz[row];
    float4* base = (float4*)(attn + (size_t)row * SS) + threadIdx.x;
    #pragma unroll
    for (int k = 1; k >= 0; k--) {
        float4 v = base[k * 512];
        v.x = __expf(v.x - m) * r;
        v.y = __expf(v.y - m) * r;
        v.z = __expf(v.z - m) * r;
        v.w = __expf(v.w - m) * r;
        __stcs(base + k * 512, v);
    }
}

extern "C" void kernel_launch(void* const* d_in, const int* in_sizes, int n_in,
                              void* d_out, int out_size)
{
    const float* Q = (const float*)d_in[0];
    const float* V = (const float*)d_in[1];
    float* out  = (float*)d_out;
    float* ctx  = out;                           // [B, S, D]
    float* attn = out + (size_t)BB * SS * DD;    // [B, S, S]

    cudaFuncSetAttribute(attn_mma_kernel,
                         cudaFuncAttributeMaxDynamicSharedMemorySize, SMEM_TOTAL);

    dim3 grid(SS / QT, BB);   // 32 x 4 = 128 CTAs
    attn_mma_kernel<<<grid, NTH, SMEM_TOTAL>>>(Q, V, ctx, attn);

    attn_norm_kernel<<<GROWS, 512>>>(attn);
}

// round 10
// speedup vs baseline: 1.3179x; 1.3179x over previous
#include <cuda_runtime.h>
#include <cuda_fp16.h>
#include <cstdint>

#define BB 4
#define SS 4096
#define DD 64
#define QT 128
#define KT 128
#define NTH 256
#define NCHUNK (SS / KT)
#define VSTR 72   // fp16 elems per smem row (144B: conflict-free ldmatrix)

#define TILE_BYTES (QT * VSTR * 2)
#define BUF_BYTES  (2 * TILE_BYTES)
#define SMEM_TOTAL (2 * BUF_BYTES)   // 73728

#define GROWS (BB * SS)

// scratch: per-row stats + per-(row, chunk) running max
__device__ float g_rowm[GROWS];
__device__ float g_rowz[GROWS];
__device__ float g_cm[(size_t)GROWS * NCHUNK];   // 2 MB

#define NEGINF __int_as_float(0xff800000)

static __device__ __forceinline__ uint32_t smem_u32(const void* p) {
    uint32_t a;
    asm("{ .reg .u64 t; cvta.to.shared.u64 t, %1; cvt.u32.u64 %0, t; }" : "=r"(a) : "l"(p));
    return a;
}

static __device__ __forceinline__ uint32_t pack_f16(float lo, float hi) {
    uint32_t r;
    asm("cvt.rn.f16x2.f32 %0, %1, %2;" : "=r"(r) : "f"(hi), "f"(lo));
    return r;
}

#define LDSM4(r, a) \
    asm volatile("ldmatrix.sync.aligned.m8n8.x4.shared.b16 {%0,%1,%2,%3}, [%4];" \
                 : "=r"((r)[0]), "=r"((r)[1]), "=r"((r)[2]), "=r"((r)[3]) : "r"(a))

#define LDSM4T(r, a) \
    asm volatile("ldmatrix.sync.aligned.m8n8.x4.trans.shared.b16 {%0,%1,%2,%3}, [%4];" \
                 : "=r"((r)[0]), "=r"((r)[1]), "=r"((r)[2]), "=r"((r)[3]) : "r"(a))

static __device__ __forceinline__ void mma16816(float* d, const uint32_t* a,
                                                uint32_t b0, uint32_t b1) {
    asm volatile(
        "mma.sync.aligned.m16n8k16.row.col.f32.f16.f16.f32 "
        "{%0,%1,%2,%3}, {%4,%5,%6,%7}, {%8,%9}, {%0,%1,%2,%3};"
        : "+f"(d[0]), "+f"(d[1]), "+f"(d[2]), "+f"(d[3])
        : "r"(a[0]), "r"(a[1]), "r"(a[2]), "r"(a[3]), "r"(b0), "r"(b1));
}

// split fp32x4 -> hi/lo fp16x2 pairs into the H/L tiles
static __device__ __forceinline__ void split_store(char* smbase, uint32_t off,
                                                   float4 v) {
    __half hx = __float2half_rn(v.x);
    __half hy = __float2half_rn(v.y);
    __half hz = __float2half_rn(v.z);
    __half hw = __float2half_rn(v.w);
    uint2 H, L;
    H.x = pack_f16(v.x, v.y);
    H.y = pack_f16(v.z, v.w);
    L.x = pack_f16(v.x - __half2float(hx), v.y - __half2float(hy));
    L.y = pack_f16(v.z - __half2float(hz), v.w - __half2float(hw));
    *(uint2*)(smbase + off)              = H;
    *(uint2*)(smbase + off + TILE_BYTES) = L;
}

// Main kernel (round-5 structure): GEMM1 -> softmax -> store p=exp(s-m_c)
// -> GEMM2. One CTA per (batch, 128-q-row strip).
__global__ void __launch_bounds__(NTH, 1)
attn_mma_kernel(const float* __restrict__ Q, const float* __restrict__ V,
                float* __restrict__ ctx_out, float* __restrict__ attn_out)
{
    extern __shared__ __align__(16) char smraw[];   // [buf0 H|L][buf1 H|L]

    const int tid  = threadIdx.x;
    const int w    = tid >> 5;
    const int lane = tid & 31;
    const int g    = lane >> 2;
    const int p    = lane & 3;
    const int b    = blockIdx.y;
    const int q0   = blockIdx.x * QT;

    const float* Qg = Q + (size_t)(b * SS + q0) * DD;
    const float* Vg = V + (size_t)b * SS * DD;

    const uint32_t sbase = smem_u32(smraw);

    const int ldq  = tid >> 4;
    const int ldd4 = (tid & 15) * 4;
    const uint32_t stoff = (uint32_t)(ldq * VSTR + ldd4) * 2;

    // ---- stage Q -> buf0 hi/lo ----
    #pragma unroll
    for (int r = 0; r < 8; r++) {
        int lin = tid + r * NTH;
        int q  = lin >> 4;
        int d4 = (lin & 15) * 4;
        float4 v = *(const float4*)(Qg + q * DD + d4);
        split_store(smraw, (uint32_t)(q * VSTR + d4) * 2, v);
    }
    __syncthreads();

    const int rA = (lane & 7) + ((lane >> 3) & 1) * 8;
    const int kA = (lane >> 4) * 8;
    const int rB = (lane & 7) + (lane >> 4) * 8;
    const int kB = ((lane >> 3) & 1) * 8;

    uint32_t qh[4][4], ql[4][4];
    #pragma unroll
    for (int ks = 0; ks < 4; ks++) {
        uint32_t off = (uint32_t)((w * 16 + rA) * VSTR + ks * 16 + kA) * 2;
        LDSM4(qh[ks], sbase + off);
        LDSM4(ql[ks], sbase + off + TILE_BYTES);
    }
    __syncthreads();

    float m0 = NEGINF, m1 = NEGINF, z0 = 0.0f, z1 = 0.0f;
    float cacc[8][4];
    #pragma unroll
    for (int j = 0; j < 8; j++)
        #pragma unroll
        for (int e = 0; e < 4; e++) cacc[j][e] = 0.0f;

    float4 pv[8];
    #pragma unroll
    for (int r = 0; r < 8; r++)
        pv[r] = *(const float4*)(Vg + (size_t)(r * 16 + ldq) * DD + ldd4);

    for (int c = 0; c < NCHUNK; c++) {
        char*    smb = smraw + (c & 1) * BUF_BYTES;
        uint32_t sb  = sbase + (c & 1) * BUF_BYTES;

        #pragma unroll
        for (int r = 0; r < 8; r++)
            split_store(smb, stoff + (uint32_t)(r * 16 * VSTR) * 2, pv[r]);
        __syncthreads();

        if (c + 1 < NCHUNK) {
            const float* vn = Vg + (size_t)((c + 1) * KT + ldq) * DD + ldd4;
            #pragma unroll
            for (int r = 0; r < 8; r++)
                pv[r] = *(const float4*)(vn + (size_t)(r * 16) * DD);
        }

        // ---- GEMM1: 3-combo fp16 split (batched, ks-outer as round 5) ----
        float sacc[16][4];
        #pragma unroll
        for (int j = 0; j < 16; j++)
            #pragma unroll
            for (int e = 0; e < 4; e++) sacc[j][e] = 0.0f;

        #pragma unroll
        for (int ks = 0; ks < 4; ks++) {
            #pragma unroll
            for (int np = 0; np < 8; np++) {
                uint32_t off = (uint32_t)((np * 16 + rB) * VSTR + ks * 16 + kB) * 2;
                uint32_t bh[4], bl[4];
                LDSM4(bh, sb + off);
                LDSM4(bl, sb + off + TILE_BYTES);
                mma16816(sacc[2 * np],     qh[ks], bh[0], bh[1]);
                mma16816(sacc[2 * np + 1], qh[ks], bh[2], bh[3]);
                mma16816(sacc[2 * np],     qh[ks], bl[0], bl[1]);
                mma16816(sacc[2 * np + 1], qh[ks], bl[2], bl[3]);
                mma16816(sacc[2 * np],     ql[ks], bh[0], bh[1]);
                mma16816(sacc[2 * np + 1], ql[ks], bh[2], bh[3]);
            }
        }

        // ---- online softmax: max, rescale, exp in place ----
        float ml0 = NEGINF, ml1 = NEGINF;
        #pragma unroll
        for (int j = 0; j < 16; j++) {
            ml0 = fmaxf(ml0, fmaxf(sacc[j][0], sacc[j][1]));
            ml1 = fmaxf(ml1, fmaxf(sacc[j][2], sacc[j][3]));
        }
        #pragma unroll
        for (int off = 1; off <= 2; off <<= 1) {
            ml0 = fmaxf(ml0, __shfl_xor_sync(0xffffffffu, ml0, off));
            ml1 = fmaxf(ml1, __shfl_xor_sync(0xffffffffu, ml1, off));
        }
        float mn0 = fmaxf(m0, ml0), mn1 = fmaxf(m1, ml1);
        float sc0 = __expf(m0 - mn0), sc1 = __expf(m1 - mn1);
        m0 = mn0; m1 = mn1;

        float s0 = 0.0f, s1 = 0.0f;
        #pragma unroll
        for (int j = 0; j < 16; j++) {
            sacc[j][0] = __expf(sacc[j][0] - mn0);
            sacc[j][1] = __expf(sacc[j][1] - mn0);
            sacc[j][2] = __expf(sacc[j][2] - mn1);
            sacc[j][3] = __expf(sacc[j][3] - mn1);
            s0 += sacc[j][0] + sacc[j][1];
            s1 += sacc[j][2] + sacc[j][3];
        }
        #pragma unroll
        for (int off = 1; off <= 2; off <<= 1) {
            s0 += __shfl_xor_sync(0xffffffffu, s0, off);
            s1 += __shfl_xor_sync(0xffffffffu, s1, off);
        }
        z0 = z0 * sc0 + s0;
        z1 = z1 * sc1 + s1;

        // ---- store p = exp(s - m_c) (batched), plus this chunk's m_c ----
        {
            float* srow0 = attn_out + (size_t)(b * SS + q0 + w * 16 + g) * SS + c * KT + 2 * p;
            float* srow1 = srow0 + (size_t)8 * SS;
            #pragma unroll
            for (int j = 0; j < 16; j++) {
                *(float2*)(srow0 + 8 * j) = make_float2(sacc[j][0], sacc[j][1]);
                *(float2*)(srow1 + 8 * j) = make_float2(sacc[j][2], sacc[j][3]);
            }
            if (p == 0) {
                int row = b * SS + q0 + w * 16 + g;
                g_cm[(size_t)row * NCHUNK + c]       = mn0;
                g_cm[(size_t)(row + 8) * NCHUNK + c] = mn1;
            }
        }

        #pragma unroll
        for (int j = 0; j < 8; j++) {
            cacc[j][0] *= sc0; cacc[j][1] *= sc0;
            cacc[j][2] *= sc1; cacc[j][3] *= sc1;
        }

        // ---- GEMM2: ctx += P(fp16) @ Vh ----
        #pragma unroll
        for (int kk = 0; kk < 8; kk++) {
            uint32_t ah[4];
            ah[0] = pack_f16(sacc[2 * kk][0],     sacc[2 * kk][1]);
            ah[1] = pack_f16(sacc[2 * kk][2],     sacc[2 * kk][3]);
            ah[2] = pack_f16(sacc[2 * kk + 1][0], sacc[2 * kk + 1][1]);
            ah[3] = pack_f16(sacc[2 * kk + 1][2], sacc[2 * kk + 1][3]);
            #pragma unroll
            for (int np = 0; np < 4; np++) {
                uint32_t off = (uint32_t)((kk * 16 + rA) * VSTR + np * 16 + kA) * 2;
                uint32_t bh[4];
                LDSM4T(bh, sb + off);
                mma16816(cacc[2 * np],     ah, bh[0], bh[1]);
                mma16816(cacc[2 * np + 1], ah, bh[2], bh[3]);
            }
        }
    }

    // ---- epilogue ----
    const float iz0 = 1.0f / z0, iz1 = 1.0f / z1;
    {
        float* crow0 = ctx_out + (size_t)(b * SS + q0 + w * 16 + g) * DD + 2 * p;
        float* crow1 = crow0 + (size_t)8 * DD;
        #pragma unroll
        for (int j = 0; j < 8; j++) {
            *(float2*)(crow0 + 8 * j) = make_float2(cacc[j][0] * iz0, cacc[j][1] * iz0);
            *(float2*)(crow1 + 8 * j) = make_float2(cacc[j][2] * iz1, cacc[j][3] * iz1);
        }
    }
    if (p == 0) {
        int row = b * SS + q0 + w * 16 + g;
        g_rowm[row]     = m0;
        g_rowz[row]     = z0;
        g_rowm[row + 8] = m1;
        g_rowz[row + 8] = z1;
    }
}

// Norm kernel: pure scale. w = p * exp(m_c - m)/Z; factor is warp-uniform
// per 128-col chunk. High columns first (L2-resident), streaming stores.
__global__ void __launch_bounds__(512)
attn_norm_kernel(float* __restrict__ attn)
{
    const int row = blockIdx.x;
    const float m  = g_rowm[row];
    const float iz = 1.0f / g_rowz[row];
    const float* cmr = g_cm + (size_t)row * NCHUNK;
    float4* base = (float4*)(attn + (size_t)row * SS) + threadIdx.x;
    #pragma unroll
    for (int k = 1; k >= 0; k--) {
        int col4  = threadIdx.x + k * 512;      // float4 index within row
        int chunk = col4 >> 5;                  // 32 float4 per 128-col chunk
        float f = __expf(cmr[chunk] - m) * iz;  // warp-uniform
        float4 v = base[k * 512];
        v.x *= f; v.y *= f; v.z *= f; v.w *= f;
        __stcs(base + k * 512, v);
    }
}

extern "C" void kernel_launch(void* const* d_in, const int* in_sizes, int n_in,
                              void* d_out, int out_size)
{
    const float* Q = (const float*)d_in[0];
    const float* V = (const float*)d_in[1];
    float* out  = (float*)d_out;
    float* ctx  = out;                           // [B, S, D]
    float* attn = out + (size_t)BB * SS * DD;    // [B, S, S]

    cudaFuncSetAttribute(attn_mma_kernel,
                         cudaFuncAttributeMaxDynamicSharedMemorySize, SMEM_TOTAL);

    dim3 grid(SS / QT, BB);   // 32 x 4 = 128 CTAs
    attn_mma_kernel<<<grid, NTH, SMEM_TOTAL>>>(Q, V, ctx, attn);

    attn_norm_kernel<<<GROWS, 512>>>(attn);
}

// round 11
// speedup vs baseline: 1.4361x; 1.0896x over previous
#include <cuda_runtime.h>
#include <cuda_fp16.h>
#include <cstdint>

#define BB 4
#define SS 4096
#define DD 64
#define QT 128
#define KT 128
#define NTH 256
#define NCHUNK (SS / KT)
#define VSTR 72     // fp16 elems per smem row (144B: conflict-free ldmatrix)
#define SSTR 132    // fp32 elems per score-stage row

#define TILE_BYTES (QT * VSTR * 2)
#define BUF_BYTES  (2 * TILE_BYTES)
#define SSTAGE_BYTES (QT * SSTR * 4)                  // 67584
#define SMEM_TOTAL (2 * BUF_BYTES + SSTAGE_BYTES)     // 141312

#define GROWS (BB * SS)

// per-row softmax stats scratch
__device__ float g_rowm[GROWS];
__device__ float g_rowz[GROWS];

#define NEGINF __int_as_float(0xff800000)

static __device__ __forceinline__ uint32_t smem_u32(const void* p) {
    uint32_t a;
    asm("{ .reg .u64 t; cvta.to.shared.u64 t, %1; cvt.u32.u64 %0, t; }" : "=r"(a) : "l"(p));
    return a;
}

static __device__ __forceinline__ uint32_t pack_f16(float lo, float hi) {
    uint32_t r;
    asm("cvt.rn.f16x2.f32 %0, %1, %2;" : "=r"(r) : "f"(hi), "f"(lo));
    return r;
}

#define LDSM4(r, a) \
    asm volatile("ldmatrix.sync.aligned.m8n8.x4.shared.b16 {%0,%1,%2,%3}, [%4];" \
                 : "=r"((r)[0]), "=r"((r)[1]), "=r"((r)[2]), "=r"((r)[3]) : "r"(a))

#define LDSM4T(r, a) \
    asm volatile("ldmatrix.sync.aligned.m8n8.x4.trans.shared.b16 {%0,%1,%2,%3}, [%4];" \
                 : "=r"((r)[0]), "=r"((r)[1]), "=r"((r)[2]), "=r"((r)[3]) : "r"(a))

static __device__ __forceinline__ void mma16816(float* d, const uint32_t* a,
                                                uint32_t b0, uint32_t b1) {
    asm volatile(
        "mma.sync.aligned.m16n8k16.row.col.f32.f16.f16.f32 "
        "{%0,%1,%2,%3}, {%4,%5,%6,%7}, {%8,%9}, {%0,%1,%2,%3};"
        : "+f"(d[0]), "+f"(d[1]), "+f"(d[2]), "+f"(d[3])
        : "r"(a[0]), "r"(a[1]), "r"(a[2]), "r"(a[3]), "r"(b0), "r"(b1));
}

// split fp32x4 -> hi/lo fp16x2 pairs into the H/L tiles
static __device__ __forceinline__ void split_store(char* smbase, uint32_t off,
                                                   float4 v) {
    __half hx = __float2half_rn(v.x);
    __half hy = __float2half_rn(v.y);
    __half hz = __float2half_rn(v.z);
    __half hw = __float2half_rn(v.w);
    uint2 H, L;
    H.x = pack_f16(v.x, v.y);
    H.y = pack_f16(v.z, v.w);
    L.x = pack_f16(v.x - __half2float(hx), v.y - __half2float(hy));
    L.y = pack_f16(v.z - __half2float(hz), v.w - __half2float(hw));
    *(uint2*)(smbase + off)              = H;
    *(uint2*)(smbase + off + TILE_BYTES) = L;
}

// Main kernel (round-5 structure + smem score epilogue).
__global__ void __launch_bounds__(NTH, 1)
attn_mma_kernel(const float* __restrict__ Q, const float* __restrict__ V,
                float* __restrict__ ctx_out, float* __restrict__ attn_out)
{
    extern __shared__ __align__(16) char smraw[];   // [buf0 H|L][buf1 H|L][sstage]
    float* sstage = (float*)(smraw + 2 * BUF_BYTES);

    const int tid  = threadIdx.x;
    const int w    = tid >> 5;
    const int lane = tid & 31;
    const int g    = lane >> 2;
    const int p    = lane & 3;
    const int b    = blockIdx.y;
    const int q0   = blockIdx.x * QT;

    const float* Qg = Q + (size_t)(b * SS + q0) * DD;
    const float* Vg = V + (size_t)b * SS * DD;

    const uint32_t sbase = smem_u32(smraw);

    const int ldq  = tid >> 4;
    const int ldd4 = (tid & 15) * 4;
    const uint32_t stoff = (uint32_t)(ldq * VSTR + ldd4) * 2;

    // ---- stage Q -> buf0 hi/lo ----
    #pragma unroll
    for (int r = 0; r < 8; r++) {
        int lin = tid + r * NTH;
        int q  = lin >> 4;
        int d4 = (lin & 15) * 4;
        float4 v = *(const float4*)(Qg + q * DD + d4);
        split_store(smraw, (uint32_t)(q * VSTR + d4) * 2, v);
    }
    __syncthreads();

    const int rA = (lane & 7) + ((lane >> 3) & 1) * 8;
    const int kA = (lane >> 4) * 8;
    const int rB = (lane & 7) + (lane >> 4) * 8;
    const int kB = ((lane >> 3) & 1) * 8;

    uint32_t qh[4][4], ql[4][4];
    #pragma unroll
    for (int ks = 0; ks < 4; ks++) {
        uint32_t off = (uint32_t)((w * 16 + rA) * VSTR + ks * 16 + kA) * 2;
        LDSM4(qh[ks], sbase + off);
        LDSM4(ql[ks], sbase + off + TILE_BYTES);
    }
    __syncthreads();

    float m0 = NEGINF, m1 = NEGINF, z0 = 0.0f, z1 = 0.0f;
    float cacc[8][4];
    #pragma unroll
    for (int j = 0; j < 8; j++)
        #pragma unroll
        for (int e = 0; e < 4; e++) cacc[j][e] = 0.0f;

    float4 pv[8];
    #pragma unroll
    for (int r = 0; r < 8; r++)
        pv[r] = *(const float4*)(Vg + (size_t)(r * 16 + ldq) * DD + ldd4);

    for (int c = 0; c < NCHUNK; c++) {
        char*    smb = smraw + (c & 1) * BUF_BYTES;
        uint32_t sb  = sbase + (c & 1) * BUF_BYTES;

        #pragma unroll
        for (int r = 0; r < 8; r++)
            split_store(smb, stoff + (uint32_t)(r * 16 * VSTR) * 2, pv[r]);
        __syncthreads();

        if (c + 1 < NCHUNK) {
            const float* vn = Vg + (size_t)((c + 1) * KT + ldq) * DD + ldd4;
            #pragma unroll
            for (int r = 0; r < 8; r++)
                pv[r] = *(const float4*)(vn + (size_t)(r * 16) * DD);
        }

        // ---- GEMM1: 3-combo fp16 split (batched, ks-outer) ----
        float sacc[16][4];
        #pragma unroll
        for (int j = 0; j < 16; j++)
            #pragma unroll
            for (int e = 0; e < 4; e++) sacc[j][e] = 0.0f;

        #pragma unroll
        for (int ks = 0; ks < 4; ks++) {
            #pragma unroll
            for (int np = 0; np < 8; np++) {
                uint32_t off = (uint32_t)((np * 16 + rB) * VSTR + ks * 16 + kB) * 2;
                uint32_t bh[4], bl[4];
                LDSM4(bh, sb + off);
                LDSM4(bl, sb + off + TILE_BYTES);
                mma16816(sacc[2 * np],     qh[ks], bh[0], bh[1]);
                mma16816(sacc[2 * np + 1], qh[ks], bh[2], bh[3]);
                mma16816(sacc[2 * np],     qh[ks], bl[0], bl[1]);
                mma16816(sacc[2 * np + 1], qh[ks], bl[2], bl[3]);
                mma16816(sacc[2 * np],     ql[ks], bh[0], bh[1]);
                mma16816(sacc[2 * np + 1], ql[ks], bh[2], bh[3]);
            }
        }

        // ---- score epilogue: scatter to smem, then coalesced STG.128 ----
        {
            float* r0 = sstage + (w * 16 + g) * SSTR;
            float* r1 = r0 + 8 * SSTR;
            #pragma unroll
            for (int np = 0; np < 8; np++) {
                *(float2*)(r0 + 16 * np + 2 * p)     = make_float2(sacc[2*np][0],   sacc[2*np][1]);
                *(float2*)(r0 + 16 * np + 8 + 2 * p) = make_float2(sacc[2*np+1][0], sacc[2*np+1][1]);
                *(float2*)(r1 + 16 * np + 2 * p)     = make_float2(sacc[2*np][2],   sacc[2*np][3]);
                *(float2*)(r1 + 16 * np + 8 + 2 * p) = make_float2(sacc[2*np+1][2], sacc[2*np+1][3]);
            }
        }
        __syncthreads();
        {
            float* abase = attn_out + (size_t)(b * SS + q0) * SS + c * KT;
            #pragma unroll
            for (int k = 0; k < 16; k++) {
                int f  = tid + k * NTH;        // 0..4095
                int r  = f >> 5;               // warp-uniform row
                int cv = f & 31;               // lane = col4
                float4 v = *(const float4*)(sstage + r * SSTR + cv * 4);
                *(float4*)(abase + (size_t)r * SS + cv * 4) = v;
            }
        }

        // ---- online softmax (identical to round 5) ----
        float ml0 = NEGINF, ml1 = NEGINF;
        #pragma unroll
        for (int j = 0; j < 16; j++) {
            ml0 = fmaxf(ml0, fmaxf(sacc[j][0], sacc[j][1]));
            ml1 = fmaxf(ml1, fmaxf(sacc[j][2], sacc[j][3]));
        }
        #pragma unroll
        for (int off = 1; off <= 2; off <<= 1) {
            ml0 = fmaxf(ml0, __shfl_xor_sync(0xffffffffu, ml0, off));
            ml1 = fmaxf(ml1, __shfl_xor_sync(0xffffffffu, ml1, off));
        }
        float mn0 = fmaxf(m0, ml0), mn1 = fmaxf(m1, ml1);
        float sc0 = __expf(m0 - mn0), sc1 = __expf(m1 - mn1);
        m0 = mn0; m1 = mn1;

        float s0 = 0.0f, s1 = 0.0f;
        #pragma unroll
        for (int j = 0; j < 16; j++) {
            sacc[j][0] = __expf(sacc[j][0] - mn0);
            sacc[j][1] = __expf(sacc[j][1] - mn0);
            sacc[j][2] = __expf(sacc[j][2] - mn1);
            sacc[j][3] = __expf(sacc[j][3] - mn1);
            s0 += sacc[j][0] + sacc[j][1];
            s1 += sacc[j][2] + sacc[j][3];
        }
        #pragma unroll
        for (int off = 1; off <= 2; off <<= 1) {
            s0 += __shfl_xor_sync(0xffffffffu, s0, off);
            s1 += __shfl_xor_sync(0xffffffffu, s1, off);
        }
        z0 = z0 * sc0 + s0;
        z1 = z1 * sc1 + s1;

        #pragma unroll
        for (int j = 0; j < 8; j++) {
            cacc[j][0] *= sc0; cacc[j][1] *= sc0;
            cacc[j][2] *= sc1; cacc[j][3] *= sc1;
        }

        // ---- GEMM2: ctx += P(fp16) @ Vh ----
        #pragma unroll
        for (int kk = 0; kk < 8; kk++) {
            uint32_t ah[4];
            ah[0] = pack_f16(sacc[2 * kk][0],     sacc[2 * kk][1]);
            ah[1] = pack_f16(sacc[2 * kk][2],     sacc[2 * kk][3]);
            ah[2] = pack_f16(sacc[2 * kk + 1][0], sacc[2 * kk + 1][1]);
            ah[3] = pack_f16(sacc[2 * kk + 1][2], sacc[2 * kk + 1][3]);
            #pragma unroll
            for (int np = 0; np < 4; np++) {
                uint32_t off = (uint32_t)((kk * 16 + rA) * VSTR + np * 16 + kA) * 2;
                uint32_t bh[4];
                LDSM4T(bh, sb + off);
                mma16816(cacc[2 * np],     ah, bh[0], bh[1]);
                mma16816(cacc[2 * np + 1], ah, bh[2], bh[3]);
            }
        }
    }

    // ---- epilogue ----
    const float iz0 = 1.0f / z0, iz1 = 1.0f / z1;
    {
        float* crow0 = ctx_out + (size_t)(b * SS + q0 + w * 16 + g) * DD + 2 * p;
        float* crow1 = crow0 + (size_t)8 * DD;
        #pragma unroll
        for (int j = 0; j < 8; j++) {
            *(float2*)(crow0 + 8 * j) = make_float2(cacc[j][0] * iz0, cacc[j][1] * iz0);
            *(float2*)(crow1 + 8 * j) = make_float2(cacc[j][2] * iz1, cacc[j][3] * iz1);
        }
    }
    if (p == 0) {
        int row = b * SS + q0 + w * 16 + g;
        g_rowm[row]     = m0;
        g_rowz[row]     = z0;
        g_rowm[row + 8] = m1;
        g_rowz[row + 8] = z1;
    }
}

// Norm kernel: w = exp(s - m)/Z in place. High columns first (L2-resident),
// allocating loads, streaming stores.
__global__ void __launch_bounds__(512)
attn_norm_kernel(float* __restrict__ attn)
{
    const int row = blockIdx.x;
    const float m = g_rowm[row];
    const float r = 1.0f / g_rowz[row];
    float4* base = (float4*)(attn + (size_t)row * SS) + threadIdx.x;
    #pragma unroll
    for (int k = 1; k >= 0; k--) {
        float4 v = base[k * 512];
        v.x = __expf(v.x - m) * r;
        v.y = __expf(v.y - m) * r;
        v.z = __expf(v.z - m) * r;
        v.w = __expf(v.w - m) * r;
        __stcs(base + k * 512, v);
    }
}

extern "C" void kernel_launch(void* const* d_in, const int* in_sizes, int n_in,
                              void* d_out, int out_size)
{
    const float* Q = (const float*)d_in[0];
    const float* V = (const float*)d_in[1];
    float* out  = (float*)d_out;
    float* ctx  = out;                           // [B, S, D]
    float* attn = out + (size_t)BB * SS * DD;    // [B, S, S]

    cudaFuncSetAttribute(attn_mma_kernel,
                         cudaFuncAttributeMaxDynamicSharedMemorySize, SMEM_TOTAL);

    dim3 grid(SS / QT, BB);   // 32 x 4 = 128 CTAs
    attn_mma_kernel<<<grid, NTH, SMEM_TOTAL>>>(Q, V, ctx, attn);

    attn_norm_kernel<<<GROWS, 512>>>(attn);
}